// round 1
// baseline (speedup 1.0000x reference)
#include <cuda_runtime.h>
#include <math.h>

#define E_MAX 160000
#define N_MAX 10000

// scratch (static __device__ -> allowed, no allocations)
__device__ float g_mix[(size_t)E_MAX * 256];   // per-edge radial MLP output
__device__ float g_y[(size_t)E_MAX * 16];      // per-edge Y_1(3),Y_2(5),Y_3(7),pad
__device__ int   g_count[N_MAX + 1];
__device__ int   g_start[N_MAX + 2];
__device__ int   g_cursor[N_MAX + 1];
__device__ int   g_esort[E_MAX];

// ---------------------------------------------------------------- zero counts
__global__ void k_zero(int n) {
    int i = blockIdx.x * blockDim.x + threadIdx.x;
    if (i <= n) g_count[i] = 0;
}

// ------------------------------------------- spherical harmonics + histogram
__global__ void k_y_hist(const float* __restrict__ vectors,
                         const int* __restrict__ receivers, int E) {
    int e = blockIdx.x * blockDim.x + threadIdx.x;
    if (e >= E) return;
    float x = vectors[3 * e + 0];
    float y = vectors[3 * e + 1];
    float z = vectors[3 * e + 2];
    float n2 = x * x + y * y + z * z;
    float inv = 1.0f / (sqrtf(n2) + 1e-12f);
    x *= inv; y *= inv; z *= inv;

    const float s3  = 1.7320508075688772f;
    const float s5  = 2.23606797749979f;
    const float s15 = 3.872983346207417f;
    const float c33 = 2.091650066335189f;    // sqrt(35/8)
    const float c32 = 10.246950765959598f;   // sqrt(105)
    const float c31 = 1.6201851746019651f;   // sqrt(21/8)
    const float c30 = 1.3228756555322954f;   // 0.5*sqrt(7)

    float yv[16];
    yv[0] = s3 * y;  yv[1] = s3 * z;  yv[2] = s3 * x;
    yv[3] = s15 * x * y;
    yv[4] = s15 * y * z;
    yv[5] = 0.5f * s5 * (3.0f * z * z - 1.0f);
    yv[6] = s15 * x * z;
    yv[7] = 0.5f * s15 * (x * x - y * y);
    yv[8]  = c33 * y * (3.0f * x * x - y * y);
    yv[9]  = c32 * x * y * z;
    yv[10] = c31 * y * (5.0f * z * z - 1.0f);
    yv[11] = c30 * z * (5.0f * z * z - 3.0f);
    yv[12] = c31 * x * (5.0f * z * z - 1.0f);
    yv[13] = 0.5f * c32 * z * (x * x - y * y);
    yv[14] = c33 * x * (x * x - 3.0f * y * y);
    yv[15] = 1.0f;

    float4* o = (float4*)(g_y + (size_t)e * 16);
    o[0] = make_float4(yv[0], yv[1], yv[2], yv[3]);
    o[1] = make_float4(yv[4], yv[5], yv[6], yv[7]);
    o[2] = make_float4(yv[8], yv[9], yv[10], yv[11]);
    o[3] = make_float4(yv[12], yv[13], yv[14], yv[15]);

    atomicAdd(&g_count[receivers[e]], 1);
}

// ---------------------------------------------------------------- CSR scan
__global__ void k_scan(int n, int E) {
    __shared__ int sums[1024];
    int t = threadIdx.x;
    int chunk = (n + 1023) >> 10;
    int b = t * chunk;
    int eidx = min(b + chunk, n);
    int s = 0;
    for (int i = b; i < eidx; i++) s += g_count[i];
    sums[t] = s;
    __syncthreads();
    for (int off = 1; off < 1024; off <<= 1) {
        int v = (t >= off) ? sums[t - off] : 0;
        __syncthreads();
        sums[t] += v;
        __syncthreads();
    }
    int pre = (t > 0) ? sums[t - 1] : 0;
    for (int i = b; i < eidx; i++) {
        g_start[i]  = pre;
        g_cursor[i] = pre;
        pre += g_count[i];
    }
    if (t == 1023) g_start[n] = E;
}

// ---------------------------------------------------------------- scatter
__global__ void k_scatter(const int* __restrict__ receivers, int E) {
    int e = blockIdx.x * blockDim.x + threadIdx.x;
    if (e >= E) return;
    int p = atomicAdd(&g_cursor[receivers[e]], 1);
    g_esort[p] = e;
}

// ---------------------------------------------------------------- radial MLP
// thread-per-edge; weights (pre-scaled) in shared, broadcast LDS.128 reads;
// per-thread h[64] lives in XOR-swizzled shared scratch (bank-conflict-free).
__global__ void __launch_bounds__(256, 1)
k_mlp(const float* __restrict__ radial,
      const float* __restrict__ w1, const float* __restrict__ w2,
      const float* __restrict__ w3, const float* __restrict__ w4, int E) {
    extern __shared__ float smem[];
    float* w1s = smem;                 // 512
    float* w2s = w1s + 512;            // 4096
    float* w3s = w2s + 4096;           // 4096
    float* w4s = w3s + 4096;           // 16384
    float* hA  = w4s + 16384;          // 256*64
    float* hB  = hA + 256 * 64;        // 256*64

    int tid = threadIdx.x;
    for (int i = tid; i < 512;   i += 256) w1s[i] = w1[i] * 0.35355339059327379f; // /sqrt(8)
    for (int i = tid; i < 4096;  i += 256) w2s[i] = w2[i] * 0.125f;
    for (int i = tid; i < 4096;  i += 256) w3s[i] = w3[i] * 0.125f;
    for (int i = tid; i < 16384; i += 256) w4s[i] = w4[i] * 0.125f;
    __syncthreads();

    int e = blockIdx.x * 256 + tid;
    if (e >= E) return;

    int lane = tid & 31;
    float* ha = hA + tid * 64;  // private, xor-swizzled by lane
    float* hb = hB + tid * 64;

    float r[8];
    {
        const float4* rp = (const float4*)(radial + (size_t)e * 8);
        float4 a = __ldg(rp), b = __ldg(rp + 1);
        r[0] = a.x; r[1] = a.y; r[2] = a.z; r[3] = a.w;
        r[4] = b.x; r[5] = b.y; r[6] = b.z; r[7] = b.w;
    }

    // ---- layer 1: 8 -> 64, silu, -> ha
    #pragma unroll 1
    for (int j0 = 0; j0 < 64; j0 += 8) {
        float acc[8] = {0, 0, 0, 0, 0, 0, 0, 0};
        #pragma unroll
        for (int k = 0; k < 8; k++) {
            const float* wp = w1s + k * 64 + j0;
            float4 wa = *(const float4*)wp;
            float4 wb = *(const float4*)(wp + 4);
            acc[0] = fmaf(r[k], wa.x, acc[0]); acc[1] = fmaf(r[k], wa.y, acc[1]);
            acc[2] = fmaf(r[k], wa.z, acc[2]); acc[3] = fmaf(r[k], wa.w, acc[3]);
            acc[4] = fmaf(r[k], wb.x, acc[4]); acc[5] = fmaf(r[k], wb.y, acc[5]);
            acc[6] = fmaf(r[k], wb.z, acc[6]); acc[7] = fmaf(r[k], wb.w, acc[7]);
        }
        #pragma unroll
        for (int j = 0; j < 8; j++) {
            float v = acc[j];
            v = v * (1.0f / (1.0f + __expf(-v)));
            ha[(j0 + j) ^ lane] = v;
        }
    }

    // ---- layer 2: 64 -> 64, silu, ha -> hb
    #pragma unroll 1
    for (int j0 = 0; j0 < 64; j0 += 8) {
        float acc[8] = {0, 0, 0, 0, 0, 0, 0, 0};
        #pragma unroll
        for (int k = 0; k < 64; k++) {
            float hk = ha[k ^ lane];
            const float* wp = w2s + k * 64 + j0;
            float4 wa = *(const float4*)wp;
            float4 wb = *(const float4*)(wp + 4);
            acc[0] = fmaf(hk, wa.x, acc[0]); acc[1] = fmaf(hk, wa.y, acc[1]);
            acc[2] = fmaf(hk, wa.z, acc[2]); acc[3] = fmaf(hk, wa.w, acc[3]);
            acc[4] = fmaf(hk, wb.x, acc[4]); acc[5] = fmaf(hk, wb.y, acc[5]);
            acc[6] = fmaf(hk, wb.z, acc[6]); acc[7] = fmaf(hk, wb.w, acc[7]);
        }
        #pragma unroll
        for (int j = 0; j < 8; j++) {
            float v = acc[j];
            v = v * (1.0f / (1.0f + __expf(-v)));
            hb[(j0 + j) ^ lane] = v;
        }
    }

    // ---- layer 3: 64 -> 64, silu, hb -> ha
    #pragma unroll 1
    for (int j0 = 0; j0 < 64; j0 += 8) {
        float acc[8] = {0, 0, 0, 0, 0, 0, 0, 0};
        #pragma unroll
        for (int k = 0; k < 64; k++) {
            float hk = hb[k ^ lane];
            const float* wp = w3s + k * 64 + j0;
            float4 wa = *(const float4*)wp;
            float4 wb = *(const float4*)(wp + 4);
            acc[0] = fmaf(hk, wa.x, acc[0]); acc[1] = fmaf(hk, wa.y, acc[1]);
            acc[2] = fmaf(hk, wa.z, acc[2]); acc[3] = fmaf(hk, wa.w, acc[3]);
            acc[4] = fmaf(hk, wb.x, acc[4]); acc[5] = fmaf(hk, wb.y, acc[5]);
            acc[6] = fmaf(hk, wb.z, acc[6]); acc[7] = fmaf(hk, wb.w, acc[7]);
        }
        #pragma unroll
        for (int j = 0; j < 8; j++) {
            float v = acc[j];
            v = v * (1.0f / (1.0f + __expf(-v)));
            ha[(j0 + j) ^ lane] = v;
        }
    }

    // ---- layer 4: 64 -> 256 (no activation), ha -> g_mix
    float* mo = g_mix + (size_t)e * 256;
    #pragma unroll 1
    for (int j0 = 0; j0 < 256; j0 += 8) {
        float acc[8] = {0, 0, 0, 0, 0, 0, 0, 0};
        #pragma unroll
        for (int k = 0; k < 64; k++) {
            float hk = ha[k ^ lane];
            const float* wp = w4s + k * 256 + j0;
            float4 wa = *(const float4*)wp;
            float4 wb = *(const float4*)(wp + 4);
            acc[0] = fmaf(hk, wa.x, acc[0]); acc[1] = fmaf(hk, wa.y, acc[1]);
            acc[2] = fmaf(hk, wa.z, acc[2]); acc[3] = fmaf(hk, wa.w, acc[3]);
            acc[4] = fmaf(hk, wb.x, acc[4]); acc[5] = fmaf(hk, wb.y, acc[5]);
            acc[6] = fmaf(hk, wb.z, acc[6]); acc[7] = fmaf(hk, wb.w, acc[7]);
        }
        *(float4*)(mo + j0)     = make_float4(acc[0], acc[1], acc[2], acc[3]);
        *(float4*)(mo + j0 + 4) = make_float4(acc[4], acc[5], acc[6], acc[7]);
    }
}

// --------------------------------------------------- gather-side reduction
// one block per node, one warp per edge (8-way), register accumulators,
// outer-product reconstruction msg[l,c,m] = (s_c*mix[l,c]) * Y[l,m].
__global__ void __launch_bounds__(256)
k_out(const float* __restrict__ node_feats, const int* __restrict__ senders,
      float* __restrict__ out, int N) {
    __shared__ float red[8 * 1024];
    int node = blockIdx.x;
    int tid = threadIdx.x;
    int w = tid >> 5, lane = tid & 31;
    int beg = g_start[node], end = g_start[node + 1];

    float acc[32];
    #pragma unroll
    for (int i = 0; i < 32; i++) acc[i] = 0.0f;

    for (int p = beg + w; p < end; p += 8) {
        int e = g_esort[p];
        int snd = senders[e];
        const float* mixp = g_mix + (size_t)e * 256;
        const float4* yp = (const float4*)(g_y + (size_t)e * 16);
        float4 ya = __ldg(yp), yb = __ldg(yp + 1), yc = __ldg(yp + 2), yd = __ldg(yp + 3);
        float yv[15] = {ya.x, ya.y, ya.z, ya.w, yb.x, yb.y, yb.z, yb.w,
                        yc.x, yc.y, yc.z, yc.w, yd.x, yd.y, yd.z};
        #pragma unroll
        for (int h = 0; h < 2; h++) {
            int c = lane + 32 * h;
            float s   = __ldg(node_feats + (size_t)snd * 64 + c);
            float sm0 = s * __ldg(mixp + c);
            float sm1 = s * __ldg(mixp + 64 + c);
            float sm2 = s * __ldg(mixp + 128 + c);
            float sm3 = s * __ldg(mixp + 192 + c);
            float* a = acc + 16 * h;
            a[0] += sm0;
            a[1] = fmaf(sm1, yv[0], a[1]);
            a[2] = fmaf(sm1, yv[1], a[2]);
            a[3] = fmaf(sm1, yv[2], a[3]);
            #pragma unroll
            for (int m = 0; m < 5; m++) a[4 + m] = fmaf(sm2, yv[3 + m], a[4 + m]);
            #pragma unroll
            for (int m = 0; m < 7; m++) a[9 + m] = fmaf(sm3, yv[8 + m], a[9 + m]);
        }
    }

    // per-warp partials to shared in final output layout
    float* rw = red + w * 1024;
    #pragma unroll
    for (int h = 0; h < 2; h++) {
        int c = lane + 32 * h;
        float* a = acc + 16 * h;
        rw[c] = a[0];
        rw[64 + c * 3 + 0] = a[1];
        rw[64 + c * 3 + 1] = a[2];
        rw[64 + c * 3 + 2] = a[3];
        #pragma unroll
        for (int m = 0; m < 5; m++) rw[256 + c * 5 + m] = a[4 + m];
        #pragma unroll
        for (int m = 0; m < 7; m++) rw[576 + c * 7 + m] = a[9 + m];
    }
    __syncthreads();

    float* outp = out + (size_t)node * 1024;
    #pragma unroll
    for (int i = 0; i < 4; i++) {
        int o = tid + 256 * i;
        float sum = 0.0f;
        #pragma unroll
        for (int ww = 0; ww < 8; ww++) sum += red[ww * 1024 + o];
        outp[o] = sum * 0.25f;   // 1/sqrt(16)
    }
}

// ---------------------------------------------------------------- launcher
extern "C" void kernel_launch(void* const* d_in, const int* in_sizes, int n_in,
                              void* d_out, int out_size) {
    const float* vectors    = (const float*)d_in[0];
    const float* node_feats = (const float*)d_in[1];
    const float* radial     = (const float*)d_in[2];
    const float* w1         = (const float*)d_in[3];
    const float* w2         = (const float*)d_in[4];
    const float* w3         = (const float*)d_in[5];
    const float* w4         = (const float*)d_in[6];
    const int*   senders    = (const int*)d_in[7];
    const int*   receivers  = (const int*)d_in[8];

    int E = in_sizes[7];
    int N = in_sizes[1] / 64;

    const int SMEM_MLP = (512 + 4096 + 4096 + 16384 + 2 * 256 * 64) * 4; // 231424
    cudaFuncSetAttribute(k_mlp, cudaFuncAttributeMaxDynamicSharedMemorySize, SMEM_MLP);

    int gE = (E + 255) / 256;
    k_zero<<<(N + 1 + 255) / 256, 256>>>(N);
    k_y_hist<<<gE, 256>>>(vectors, receivers, E);
    k_scan<<<1, 1024>>>(N, E);
    k_scatter<<<gE, 256>>>(receivers, E);
    k_mlp<<<gE, 256, SMEM_MLP>>>(radial, w1, w2, w3, w4, E);
    k_out<<<N, 256>>>(node_feats, senders, (float*)d_out, N);
}

// round 2
// speedup vs baseline: 1.0288x; 1.0288x over previous
#include <cuda_runtime.h>
#include <math.h>

#define E_MAX 160000
#define N_MAX 10000

// scratch (static __device__ -> allowed, no allocations)
__device__ float g_mix[(size_t)E_MAX * 256];   // per-edge radial MLP output
__device__ float g_y[(size_t)E_MAX * 16];      // per-edge Y_1(3),Y_2(5),Y_3(7),pad
__device__ int   g_count[N_MAX + 1];
__device__ int   g_start[N_MAX + 2];
__device__ int   g_cursor[N_MAX + 1];
__device__ int   g_esort[E_MAX];

// ---------------- packed f32x2 helpers (exact fp32, 2 FMAs / issue) ----------
__device__ __forceinline__ unsigned long long splat2(float x) {
    unsigned long long r;
    unsigned u = __float_as_uint(x);
    asm("mov.b64 %0, {%1, %1};" : "=l"(r) : "r"(u));
    return r;
}
__device__ __forceinline__ void fma2(unsigned long long& acc,
                                     unsigned long long a, unsigned long long b) {
    asm("fma.rn.f32x2 %0, %1, %2, %0;" : "+l"(acc) : "l"(a), "l"(b));
}
__device__ __forceinline__ float2 unpack2(unsigned long long v) {
    unsigned lo, hi;
    asm("mov.b64 {%0, %1}, %2;" : "=r"(lo), "=r"(hi) : "l"(v));
    return make_float2(__uint_as_float(lo), __uint_as_float(hi));
}
__device__ __forceinline__ float silu(float v) {
    return v * (1.0f / (1.0f + __expf(-v)));
}

// ---------------------------------------------------------------- zero counts
__global__ void k_zero(int n) {
    int i = blockIdx.x * blockDim.x + threadIdx.x;
    if (i <= n) g_count[i] = 0;
}

// ------------------------------------------- spherical harmonics + histogram
__global__ void k_y_hist(const float* __restrict__ vectors,
                         const int* __restrict__ receivers, int E) {
    int e = blockIdx.x * blockDim.x + threadIdx.x;
    if (e >= E) return;
    float x = vectors[3 * e + 0];
    float y = vectors[3 * e + 1];
    float z = vectors[3 * e + 2];
    float n2 = x * x + y * y + z * z;
    float inv = 1.0f / (sqrtf(n2) + 1e-12f);
    x *= inv; y *= inv; z *= inv;

    const float s3  = 1.7320508075688772f;
    const float s5  = 2.23606797749979f;
    const float s15 = 3.872983346207417f;
    const float c33 = 2.091650066335189f;
    const float c32 = 10.246950765959598f;
    const float c31 = 1.6201851746019651f;
    const float c30 = 1.3228756555322954f;

    float yv[16];
    yv[0] = s3 * y;  yv[1] = s3 * z;  yv[2] = s3 * x;
    yv[3] = s15 * x * y;
    yv[4] = s15 * y * z;
    yv[5] = 0.5f * s5 * (3.0f * z * z - 1.0f);
    yv[6] = s15 * x * z;
    yv[7] = 0.5f * s15 * (x * x - y * y);
    yv[8]  = c33 * y * (3.0f * x * x - y * y);
    yv[9]  = c32 * x * y * z;
    yv[10] = c31 * y * (5.0f * z * z - 1.0f);
    yv[11] = c30 * z * (5.0f * z * z - 3.0f);
    yv[12] = c31 * x * (5.0f * z * z - 1.0f);
    yv[13] = 0.5f * c32 * z * (x * x - y * y);
    yv[14] = c33 * x * (x * x - 3.0f * y * y);
    yv[15] = 1.0f;

    float4* o = (float4*)(g_y + (size_t)e * 16);
    o[0] = make_float4(yv[0], yv[1], yv[2], yv[3]);
    o[1] = make_float4(yv[4], yv[5], yv[6], yv[7]);
    o[2] = make_float4(yv[8], yv[9], yv[10], yv[11]);
    o[3] = make_float4(yv[12], yv[13], yv[14], yv[15]);

    atomicAdd(&g_count[receivers[e]], 1);
}

// ---------------------------------------------------------------- CSR scan
__global__ void k_scan(int n, int E) {
    __shared__ int sums[1024];
    int t = threadIdx.x;
    int chunk = (n + 1023) >> 10;
    int b = t * chunk;
    int eidx = min(b + chunk, n);
    int s = 0;
    for (int i = b; i < eidx; i++) s += g_count[i];
    sums[t] = s;
    __syncthreads();
    for (int off = 1; off < 1024; off <<= 1) {
        int v = (t >= off) ? sums[t - off] : 0;
        __syncthreads();
        sums[t] += v;
        __syncthreads();
    }
    int pre = (t > 0) ? sums[t - 1] : 0;
    for (int i = b; i < eidx; i++) {
        g_start[i]  = pre;
        g_cursor[i] = pre;
        pre += g_count[i];
    }
    if (t == 1023) g_start[n] = E;
}

// ---------------------------------------------------------------- scatter
__global__ void k_scatter(const int* __restrict__ receivers, int E) {
    int e = blockIdx.x * blockDim.x + threadIdx.x;
    if (e >= E) return;
    int p = atomicAdd(&g_cursor[receivers[e]], 1);
    g_esort[p] = e;
}

// ---------------------------------------------------------------- radial MLP
// thread-per-edge; weights (pre-scaled) in shared (broadcast LDS.128),
// per-thread h[64] in XOR-swizzled shared; packed f32x2 FMAs, 16-wide j tile.
__global__ void __launch_bounds__(256, 1)
k_mlp(const float* __restrict__ radial,
      const float* __restrict__ w1, const float* __restrict__ w2,
      const float* __restrict__ w3, const float* __restrict__ w4, int E) {
    extern __shared__ float smem[];
    float* w1s = smem;                 // 512
    float* w2s = w1s + 512;            // 4096
    float* w3s = w2s + 4096;           // 4096
    float* w4s = w3s + 4096;           // 16384
    float* hA  = w4s + 16384;          // 256*64
    float* hB  = hA + 256 * 64;        // 256*64

    int tid = threadIdx.x;
    for (int i = tid; i < 512;   i += 256) w1s[i] = w1[i] * 0.35355339059327379f;
    for (int i = tid; i < 4096;  i += 256) w2s[i] = w2[i] * 0.125f;
    for (int i = tid; i < 4096;  i += 256) w3s[i] = w3[i] * 0.125f;
    for (int i = tid; i < 16384; i += 256) w4s[i] = w4[i] * 0.125f;
    __syncthreads();

    int e = blockIdx.x * 256 + tid;
    if (e >= E) return;

    int lane = tid & 31;
    float* ha = hA + tid * 64;  // private, xor-swizzled by lane
    float* hb = hB + tid * 64;

    unsigned long long r2[8];
    {
        const float4* rp = (const float4*)(radial + (size_t)e * 8);
        float4 a = __ldg(rp), b = __ldg(rp + 1);
        r2[0] = splat2(a.x); r2[1] = splat2(a.y); r2[2] = splat2(a.z); r2[3] = splat2(a.w);
        r2[4] = splat2(b.x); r2[5] = splat2(b.y); r2[6] = splat2(b.z); r2[7] = splat2(b.w);
    }

    // ---- layer 1: 8 -> 64, silu, -> ha
    #pragma unroll 1
    for (int j0 = 0; j0 < 64; j0 += 16) {
        unsigned long long acc[8] = {0, 0, 0, 0, 0, 0, 0, 0};
        #pragma unroll
        for (int k = 0; k < 8; k++) {
            const unsigned long long* wp = (const unsigned long long*)(w1s + k * 64 + j0);
            ulonglong2 wa = *(const ulonglong2*)(wp + 0);
            ulonglong2 wb = *(const ulonglong2*)(wp + 2);
            ulonglong2 wc = *(const ulonglong2*)(wp + 4);
            ulonglong2 wd = *(const ulonglong2*)(wp + 6);
            fma2(acc[0], r2[k], wa.x); fma2(acc[1], r2[k], wa.y);
            fma2(acc[2], r2[k], wb.x); fma2(acc[3], r2[k], wb.y);
            fma2(acc[4], r2[k], wc.x); fma2(acc[5], r2[k], wc.y);
            fma2(acc[6], r2[k], wd.x); fma2(acc[7], r2[k], wd.y);
        }
        #pragma unroll
        for (int i = 0; i < 8; i++) {
            float2 v = unpack2(acc[i]);
            ha[(j0 + 2 * i)     ^ lane] = silu(v.x);
            ha[(j0 + 2 * i + 1) ^ lane] = silu(v.y);
        }
    }

    // ---- layer 2: 64 -> 64, silu, ha -> hb
    #pragma unroll 1
    for (int j0 = 0; j0 < 64; j0 += 16) {
        unsigned long long acc[8] = {0, 0, 0, 0, 0, 0, 0, 0};
        #pragma unroll
        for (int k = 0; k < 64; k++) {
            unsigned long long hk2 = splat2(ha[k ^ lane]);
            const unsigned long long* wp = (const unsigned long long*)(w2s + k * 64 + j0);
            ulonglong2 wa = *(const ulonglong2*)(wp + 0);
            ulonglong2 wb = *(const ulonglong2*)(wp + 2);
            ulonglong2 wc = *(const ulonglong2*)(wp + 4);
            ulonglong2 wd = *(const ulonglong2*)(wp + 6);
            fma2(acc[0], hk2, wa.x); fma2(acc[1], hk2, wa.y);
            fma2(acc[2], hk2, wb.x); fma2(acc[3], hk2, wb.y);
            fma2(acc[4], hk2, wc.x); fma2(acc[5], hk2, wc.y);
            fma2(acc[6], hk2, wd.x); fma2(acc[7], hk2, wd.y);
        }
        #pragma unroll
        for (int i = 0; i < 8; i++) {
            float2 v = unpack2(acc[i]);
            hb[(j0 + 2 * i)     ^ lane] = silu(v.x);
            hb[(j0 + 2 * i + 1) ^ lane] = silu(v.y);
        }
    }

    // ---- layer 3: 64 -> 64, silu, hb -> ha
    #pragma unroll 1
    for (int j0 = 0; j0 < 64; j0 += 16) {
        unsigned long long acc[8] = {0, 0, 0, 0, 0, 0, 0, 0};
        #pragma unroll
        for (int k = 0; k < 64; k++) {
            unsigned long long hk2 = splat2(hb[k ^ lane]);
            const unsigned long long* wp = (const unsigned long long*)(w3s + k * 64 + j0);
            ulonglong2 wa = *(const ulonglong2*)(wp + 0);
            ulonglong2 wb = *(const ulonglong2*)(wp + 2);
            ulonglong2 wc = *(const ulonglong2*)(wp + 4);
            ulonglong2 wd = *(const ulonglong2*)(wp + 6);
            fma2(acc[0], hk2, wa.x); fma2(acc[1], hk2, wa.y);
            fma2(acc[2], hk2, wb.x); fma2(acc[3], hk2, wb.y);
            fma2(acc[4], hk2, wc.x); fma2(acc[5], hk2, wc.y);
            fma2(acc[6], hk2, wd.x); fma2(acc[7], hk2, wd.y);
        }
        #pragma unroll
        for (int i = 0; i < 8; i++) {
            float2 v = unpack2(acc[i]);
            ha[(j0 + 2 * i)     ^ lane] = silu(v.x);
            ha[(j0 + 2 * i + 1) ^ lane] = silu(v.y);
        }
    }

    // ---- layer 4: 64 -> 256 (no activation), ha -> g_mix (packed stores)
    float* mo = g_mix + (size_t)e * 256;
    #pragma unroll 1
    for (int j0 = 0; j0 < 256; j0 += 16) {
        unsigned long long acc[8] = {0, 0, 0, 0, 0, 0, 0, 0};
        #pragma unroll
        for (int k = 0; k < 64; k++) {
            unsigned long long hk2 = splat2(ha[k ^ lane]);
            const unsigned long long* wp = (const unsigned long long*)(w4s + k * 256 + j0);
            ulonglong2 wa = *(const ulonglong2*)(wp + 0);
            ulonglong2 wb = *(const ulonglong2*)(wp + 2);
            ulonglong2 wc = *(const ulonglong2*)(wp + 4);
            ulonglong2 wd = *(const ulonglong2*)(wp + 6);
            fma2(acc[0], hk2, wa.x); fma2(acc[1], hk2, wa.y);
            fma2(acc[2], hk2, wb.x); fma2(acc[3], hk2, wb.y);
            fma2(acc[4], hk2, wc.x); fma2(acc[5], hk2, wc.y);
            fma2(acc[6], hk2, wd.x); fma2(acc[7], hk2, wd.y);
        }
        // packed u64 pairs are exactly two consecutive floats -> direct stores
        ulonglong2* op = (ulonglong2*)(mo + j0);
        op[0] = make_ulonglong2(acc[0], acc[1]);
        op[1] = make_ulonglong2(acc[2], acc[3]);
        op[2] = make_ulonglong2(acc[4], acc[5]);
        op[3] = make_ulonglong2(acc[6], acc[7]);
    }
}

// --------------------------------------------------- gather-side reduction
__global__ void __launch_bounds__(256)
k_out(const float* __restrict__ node_feats, const int* __restrict__ senders,
      float* __restrict__ out, int N) {
    __shared__ float red[8 * 1024];
    int node = blockIdx.x;
    int tid = threadIdx.x;
    int w = tid >> 5, lane = tid & 31;
    int beg = g_start[node], end = g_start[node + 1];

    float acc[32];
    #pragma unroll
    for (int i = 0; i < 32; i++) acc[i] = 0.0f;

    for (int p = beg + w; p < end; p += 8) {
        int e = g_esort[p];
        int snd = senders[e];
        const float* mixp = g_mix + (size_t)e * 256;
        const float4* yp = (const float4*)(g_y + (size_t)e * 16);
        float4 ya = __ldg(yp), yb = __ldg(yp + 1), yc = __ldg(yp + 2), yd = __ldg(yp + 3);
        float yv[15] = {ya.x, ya.y, ya.z, ya.w, yb.x, yb.y, yb.z, yb.w,
                        yc.x, yc.y, yc.z, yc.w, yd.x, yd.y, yd.z};
        #pragma unroll
        for (int h = 0; h < 2; h++) {
            int c = lane + 32 * h;
            float s   = __ldg(node_feats + (size_t)snd * 64 + c);
            float sm0 = s * __ldg(mixp + c);
            float sm1 = s * __ldg(mixp + 64 + c);
            float sm2 = s * __ldg(mixp + 128 + c);
            float sm3 = s * __ldg(mixp + 192 + c);
            float* a = acc + 16 * h;
            a[0] += sm0;
            a[1] = fmaf(sm1, yv[0], a[1]);
            a[2] = fmaf(sm1, yv[1], a[2]);
            a[3] = fmaf(sm1, yv[2], a[3]);
            #pragma unroll
            for (int m = 0; m < 5; m++) a[4 + m] = fmaf(sm2, yv[3 + m], a[4 + m]);
            #pragma unroll
            for (int m = 0; m < 7; m++) a[9 + m] = fmaf(sm3, yv[8 + m], a[9 + m]);
        }
    }

    float* rw = red + w * 1024;
    #pragma unroll
    for (int h = 0; h < 2; h++) {
        int c = lane + 32 * h;
        float* a = acc + 16 * h;
        rw[c] = a[0];
        rw[64 + c * 3 + 0] = a[1];
        rw[64 + c * 3 + 1] = a[2];
        rw[64 + c * 3 + 2] = a[3];
        #pragma unroll
        for (int m = 0; m < 5; m++) rw[256 + c * 5 + m] = a[4 + m];
        #pragma unroll
        for (int m = 0; m < 7; m++) rw[576 + c * 7 + m] = a[9 + m];
    }
    __syncthreads();

    float* outp = out + (size_t)node * 1024;
    #pragma unroll
    for (int i = 0; i < 4; i++) {
        int o = tid + 256 * i;
        float sum = 0.0f;
        #pragma unroll
        for (int ww = 0; ww < 8; ww++) sum += red[ww * 1024 + o];
        outp[o] = sum * 0.25f;   // 1/sqrt(16)
    }
}

// ---------------------------------------------------------------- launcher
extern "C" void kernel_launch(void* const* d_in, const int* in_sizes, int n_in,
                              void* d_out, int out_size) {
    const float* vectors    = (const float*)d_in[0];
    const float* node_feats = (const float*)d_in[1];
    const float* radial     = (const float*)d_in[2];
    const float* w1         = (const float*)d_in[3];
    const float* w2         = (const float*)d_in[4];
    const float* w3         = (const float*)d_in[5];
    const float* w4         = (const float*)d_in[6];
    const int*   senders    = (const int*)d_in[7];
    const int*   receivers  = (const int*)d_in[8];

    int E = in_sizes[7];
    int N = in_sizes[1] / 64;

    const int SMEM_MLP = (512 + 4096 + 4096 + 16384 + 2 * 256 * 64) * 4; // 231424
    cudaFuncSetAttribute(k_mlp, cudaFuncAttributeMaxDynamicSharedMemorySize, SMEM_MLP);

    int gE = (E + 255) / 256;
    // order chosen so the ncu-profiled launch slot lands on k_mlp
    k_zero<<<(N + 1 + 255) / 256, 256>>>(N);
    k_y_hist<<<gE, 256>>>(vectors, receivers, E);
    k_scan<<<1, 1024>>>(N, E);
    k_mlp<<<gE, 256, SMEM_MLP>>>(radial, w1, w2, w3, w4, E);
    k_scatter<<<gE, 256>>>(receivers, E);
    k_out<<<N, 256>>>(node_feats, senders, (float*)d_out, N);
}